// round 11
// baseline (speedup 1.0000x reference)
#include <cuda_runtime.h>

// InterpreterUnit: per-row branch select.
//   inputs   [N, 131] fp32   (cols 0..2 = opcode flags, cols 3..130 = payload)
//   children [2, N, 128] fp32
//   arities  [N] int32 OR int64 (JAX x64 ambiguity -> detected at runtime)
//   out      [N, 128] fp32
//
// Warp-per-row mapping: the branch condition is per-row, so control flow is
// warp-uniform (zero divergence) and each branch arm loads only what it needs.

__device__ int g_arity_is64;

// Detect arities element width. Viewed as int32 words, an int64 buffer of
// values in {0,1,2} (little-endian) has ALL odd words == 0; an int32 buffer
// of random values in {0,1,2} does not (P ~ (1/3)^4096). Reads only the
// first 8192 int32 words (32 KB), safe under either dtype for N >= 8192.
__global__ void detect_arity_width_kernel(const int* __restrict__ ar)
{
    __shared__ int red[8];
    int acc = 0;
    for (int i = threadIdx.x; i < 4096; i += 256)
        acc |= ar[2 * i + 1];
    #pragma unroll
    for (int o = 16; o; o >>= 1)
        acc |= __shfl_xor_sync(0xFFFFFFFFu, acc, o);
    if ((threadIdx.x & 31) == 0) red[threadIdx.x >> 5] = acc;
    __syncthreads();
    if (threadIdx.x == 0) {
        int a = 0;
        #pragma unroll
        for (int i = 0; i < 8; i++) a |= red[i];
        g_arity_is64 = (a == 0) ? 1 : 0;
    }
}

__global__ __launch_bounds__(256, 8)
void InterpreterUnit_5858335392361_kernel(
    const float* __restrict__ inputs,
    const float* __restrict__ children,
    const int*   __restrict__ arities32,   // raw words; width per g_arity_is64
    float* __restrict__ out,
    int n)
{
    const int gwarp = (int)((blockIdx.x * (unsigned)blockDim.x + threadIdx.x) >> 5);
    const int lane  = threadIdx.x & 31;
    if (gwarp >= n) return;

    const long long row = gwarp;

    const float* in_row = inputs + row * 131LL;
    // Broadcast loads: all 32 lanes hit the same address -> 1 transaction each.
    const float f0 = __ldg(in_row + 0);
    const float f1 = __ldg(in_row + 1);
    const float f2 = __ldg(in_row + 2);

    const float4* __restrict__ c0 =
        reinterpret_cast<const float4*>(children + row * 128LL);
    const float4* __restrict__ c1 =
        reinterpret_cast<const float4*>(children + (long long)n * 128LL + row * 128LL);
    float4* __restrict__ o = reinterpret_cast<float4*>(out + row * 128LL);

    float4 r;
    if (f0 > 0.0f) {                       // add
        const float4 a = __ldg(c0 + lane);
        const float4 b = __ldg(c1 + lane);
        r.x = a.x + b.x; r.y = a.y + b.y; r.z = a.z + b.z; r.w = a.w + b.w;
    } else if (f1 > 0.0f) {                // mul
        const float4 a = __ldg(c0 + lane);
        const float4 b = __ldg(c1 + lane);
        r.x = a.x * b.x; r.y = a.y * b.y; r.z = a.z * b.z; r.w = a.w * b.w;
    } else if (f2 > 0.0f) {                // sub / neg
        const long long aidx = g_arity_is64 ? (row << 1) : row;  // low word holds value
        const int ar = __ldg(arities32 + aidx);
        const float4 a = __ldg(c0 + lane);
        if (ar == 1) {                     // unary: -c0
            r.x = -a.x; r.y = -a.y; r.z = -a.z; r.w = -a.w;
        } else {                           // binary: c0 - c1
            const float4 b = __ldg(c1 + lane);
            r.x = a.x - b.x; r.y = a.y - b.y; r.z = a.z - b.z; r.w = a.w - b.w;
        }
    } else {                               // passthrough: inputs[:, 3:]
        // Row stride 131 floats -> +3 offset is not 16B aligned; scalar loads.
        const float* p = in_row + 3 + lane * 4;
        r.x = __ldg(p + 0);
        r.y = __ldg(p + 1);
        r.z = __ldg(p + 2);
        r.w = __ldg(p + 3);
    }
    o[lane] = r;
}

extern "C" void kernel_launch(void* const* d_in, const int* in_sizes, int n_in,
                              void* d_out, int out_size)
{
    // Identify the three tensors by element count: N, 131N, 256N.
    int i_children = 0, i_inputs = 0, i_arities = 0;
    for (int i = 1; i < n_in; i++) {
        if (in_sizes[i] > in_sizes[i_children]) i_children = i;
        if (in_sizes[i] < in_sizes[i_arities])  i_arities  = i;
    }
    for (int i = 0; i < n_in; i++)
        if (i != i_children && i != i_arities) i_inputs = i;

    const float* inputs   = (const float*)d_in[i_inputs];    // [N, 131]
    const float* children = (const float*)d_in[i_children];  // [2, N, 128]
    const int*   arities  = (const int*)d_in[i_arities];     // [N] (32- or 64-bit)
    float*       out      = (float*)d_out;                   // [N, 128]

    const int n = in_sizes[i_children] / 256;                // N

    detect_arity_width_kernel<<<1, 256>>>(arities);

    // One warp per row: 256 threads/block = 8 rows/block.
    const int blocks = (n + 7) / 8;
    InterpreterUnit_5858335392361_kernel<<<blocks, 256>>>(
        inputs, children, arities, out, n);
}

// round 12
// speedup vs baseline: 1.0010x; 1.0010x over previous
#include <cuda_runtime.h>

// InterpreterUnit: per-row branch select.
//   inputs   [N, 131] fp32   (cols 0..2 = opcode flags, cols 3..130 = payload)
//   children [2, N, 128] fp32
//   arities  [N] int32 OR int64 (JAX x64 ambiguity -> detected at runtime)
//   out      [N, 128] fp32
//
// Warp-per-row mapping: the branch condition is per-row, so control flow is
// warp-uniform (zero divergence) and each branch arm loads only what it needs.

__device__ int g_arity_is64;

// Detect arities element width. Viewed as int32 words, an int64 buffer of
// values in {0,1,2} (little-endian) has ALL odd words == 0; an int32 buffer
// of random values in {0,1,2} does not (P ~ (1/3)^4096). Reads only the
// first 8192 int32 words (32 KB), safe under either dtype for N >= 8192.
__global__ void detect_arity_width_kernel(const int* __restrict__ ar)
{
    __shared__ int red[8];
    int acc = 0;
    for (int i = threadIdx.x; i < 4096; i += 256)
        acc |= ar[2 * i + 1];
    #pragma unroll
    for (int o = 16; o; o >>= 1)
        acc |= __shfl_xor_sync(0xFFFFFFFFu, acc, o);
    if ((threadIdx.x & 31) == 0) red[threadIdx.x >> 5] = acc;
    __syncthreads();
    if (threadIdx.x == 0) {
        int a = 0;
        #pragma unroll
        for (int i = 0; i < 8; i++) a |= red[i];
        g_arity_is64 = (a == 0) ? 1 : 0;
    }
}

__global__ __launch_bounds__(256, 8)
void InterpreterUnit_5858335392361_kernel(
    const float* __restrict__ inputs,
    const float* __restrict__ children,
    const int*   __restrict__ arities32,   // raw words; width per g_arity_is64
    float* __restrict__ out,
    int n)
{
    const int gwarp = (int)((blockIdx.x * (unsigned)blockDim.x + threadIdx.x) >> 5);
    const int lane  = threadIdx.x & 31;
    if (gwarp >= n) return;

    const long long row = gwarp;

    const float* in_row = inputs + row * 131LL;
    // Broadcast loads: all 32 lanes hit the same address -> 1 transaction each.
    const float f0 = __ldg(in_row + 0);
    const float f1 = __ldg(in_row + 1);
    const float f2 = __ldg(in_row + 2);

    const float4* __restrict__ c0 =
        reinterpret_cast<const float4*>(children + row * 128LL);
    const float4* __restrict__ c1 =
        reinterpret_cast<const float4*>(children + (long long)n * 128LL + row * 128LL);
    float4* __restrict__ o = reinterpret_cast<float4*>(out + row * 128LL);

    float4 r;
    if (f0 > 0.0f) {                       // add
        const float4 a = __ldg(c0 + lane);
        const float4 b = __ldg(c1 + lane);
        r.x = a.x + b.x; r.y = a.y + b.y; r.z = a.z + b.z; r.w = a.w + b.w;
    } else if (f1 > 0.0f) {                // mul
        const float4 a = __ldg(c0 + lane);
        const float4 b = __ldg(c1 + lane);
        r.x = a.x * b.x; r.y = a.y * b.y; r.z = a.z * b.z; r.w = a.w * b.w;
    } else if (f2 > 0.0f) {                // sub / neg
        const long long aidx = g_arity_is64 ? (row << 1) : row;  // low word holds value
        const int ar = __ldg(arities32 + aidx);
        const float4 a = __ldg(c0 + lane);
        if (ar == 1) {                     // unary: -c0
            r.x = -a.x; r.y = -a.y; r.z = -a.z; r.w = -a.w;
        } else {                           // binary: c0 - c1
            const float4 b = __ldg(c1 + lane);
            r.x = a.x - b.x; r.y = a.y - b.y; r.z = a.z - b.z; r.w = a.w - b.w;
        }
    } else {                               // passthrough: inputs[:, 3:]
        // Row stride 131 floats -> +3 offset is not 16B aligned; scalar loads.
        const float* p = in_row + 3 + lane * 4;
        r.x = __ldg(p + 0);
        r.y = __ldg(p + 1);
        r.z = __ldg(p + 2);
        r.w = __ldg(p + 3);
    }
    o[lane] = r;
}

extern "C" void kernel_launch(void* const* d_in, const int* in_sizes, int n_in,
                              void* d_out, int out_size)
{
    // Identify the three tensors by element count: N, 131N, 256N.
    int i_children = 0, i_inputs = 0, i_arities = 0;
    for (int i = 1; i < n_in; i++) {
        if (in_sizes[i] > in_sizes[i_children]) i_children = i;
        if (in_sizes[i] < in_sizes[i_arities])  i_arities  = i;
    }
    for (int i = 0; i < n_in; i++)
        if (i != i_children && i != i_arities) i_inputs = i;

    const float* inputs   = (const float*)d_in[i_inputs];    // [N, 131]
    const float* children = (const float*)d_in[i_children];  // [2, N, 128]
    const int*   arities  = (const int*)d_in[i_arities];     // [N] (32- or 64-bit)
    float*       out      = (float*)d_out;                   // [N, 128]

    const int n = in_sizes[i_children] / 256;                // N

    detect_arity_width_kernel<<<1, 256>>>(arities);

    // One warp per row: 256 threads/block = 8 rows/block.
    const int blocks = (n + 7) / 8;
    InterpreterUnit_5858335392361_kernel<<<blocks, 256>>>(
        inputs, children, arities, out, n);
}

// round 13
// speedup vs baseline: 1.0013x; 1.0003x over previous
#include <cuda_runtime.h>

// InterpreterUnit: per-row branch select.
//   inputs   [N, 131] fp32   (cols 0..2 = opcode flags, cols 3..130 = payload)
//   children [2, N, 128] fp32
//   arities  [N] int32 OR int64 (JAX x64 ambiguity -> detected at runtime)
//   out      [N, 128] fp32
//
// Warp-per-row mapping: the branch condition is per-row, so control flow is
// warp-uniform (zero divergence) and each branch arm loads only what it needs.

__device__ int g_arity_is64;

// Detect arities element width. Viewed as int32 words, an int64 buffer of
// values in {0,1,2} (little-endian) has ALL odd words == 0; an int32 buffer
// of random values in {0,1,2} does not (P ~ (1/3)^4096). Reads only the
// first 8192 int32 words (32 KB), safe under either dtype for N >= 8192.
__global__ void detect_arity_width_kernel(const int* __restrict__ ar)
{
    __shared__ int red[8];
    int acc = 0;
    for (int i = threadIdx.x; i < 4096; i += 256)
        acc |= ar[2 * i + 1];
    #pragma unroll
    for (int o = 16; o; o >>= 1)
        acc |= __shfl_xor_sync(0xFFFFFFFFu, acc, o);
    if ((threadIdx.x & 31) == 0) red[threadIdx.x >> 5] = acc;
    __syncthreads();
    if (threadIdx.x == 0) {
        int a = 0;
        #pragma unroll
        for (int i = 0; i < 8; i++) a |= red[i];
        g_arity_is64 = (a == 0) ? 1 : 0;
    }
}

__global__ __launch_bounds__(256, 8)
void InterpreterUnit_5858335392361_kernel(
    const float* __restrict__ inputs,
    const float* __restrict__ children,
    const int*   __restrict__ arities32,   // raw words; width per g_arity_is64
    float* __restrict__ out,
    int n)
{
    const int gwarp = (int)((blockIdx.x * (unsigned)blockDim.x + threadIdx.x) >> 5);
    const int lane  = threadIdx.x & 31;
    if (gwarp >= n) return;

    const long long row = gwarp;

    const float* in_row = inputs + row * 131LL;
    // Broadcast loads: all 32 lanes hit the same address -> 1 transaction each.
    const float f0 = __ldg(in_row + 0);
    const float f1 = __ldg(in_row + 1);
    const float f2 = __ldg(in_row + 2);

    const float4* __restrict__ c0 =
        reinterpret_cast<const float4*>(children + row * 128LL);
    const float4* __restrict__ c1 =
        reinterpret_cast<const float4*>(children + (long long)n * 128LL + row * 128LL);
    float4* __restrict__ o = reinterpret_cast<float4*>(out + row * 128LL);

    float4 r;
    if (f0 > 0.0f) {                       // add
        const float4 a = __ldg(c0 + lane);
        const float4 b = __ldg(c1 + lane);
        r.x = a.x + b.x; r.y = a.y + b.y; r.z = a.z + b.z; r.w = a.w + b.w;
    } else if (f1 > 0.0f) {                // mul
        const float4 a = __ldg(c0 + lane);
        const float4 b = __ldg(c1 + lane);
        r.x = a.x * b.x; r.y = a.y * b.y; r.z = a.z * b.z; r.w = a.w * b.w;
    } else if (f2 > 0.0f) {                // sub / neg
        const long long aidx = g_arity_is64 ? (row << 1) : row;  // low word holds value
        const int ar = __ldg(arities32 + aidx);
        const float4 a = __ldg(c0 + lane);
        if (ar == 1) {                     // unary: -c0
            r.x = -a.x; r.y = -a.y; r.z = -a.z; r.w = -a.w;
        } else {                           // binary: c0 - c1
            const float4 b = __ldg(c1 + lane);
            r.x = a.x - b.x; r.y = a.y - b.y; r.z = a.z - b.z; r.w = a.w - b.w;
        }
    } else {                               // passthrough: inputs[:, 3:]
        // Row stride 131 floats -> +3 offset is not 16B aligned; scalar loads.
        const float* p = in_row + 3 + lane * 4;
        r.x = __ldg(p + 0);
        r.y = __ldg(p + 1);
        r.z = __ldg(p + 2);
        r.w = __ldg(p + 3);
    }
    o[lane] = r;
}

extern "C" void kernel_launch(void* const* d_in, const int* in_sizes, int n_in,
                              void* d_out, int out_size)
{
    // Identify the three tensors by element count: N, 131N, 256N.
    int i_children = 0, i_inputs = 0, i_arities = 0;
    for (int i = 1; i < n_in; i++) {
        if (in_sizes[i] > in_sizes[i_children]) i_children = i;
        if (in_sizes[i] < in_sizes[i_arities])  i_arities  = i;
    }
    for (int i = 0; i < n_in; i++)
        if (i != i_children && i != i_arities) i_inputs = i;

    const float* inputs   = (const float*)d_in[i_inputs];    // [N, 131]
    const float* children = (const float*)d_in[i_children];  // [2, N, 128]
    const int*   arities  = (const int*)d_in[i_arities];     // [N] (32- or 64-bit)
    float*       out      = (float*)d_out;                   // [N, 128]

    const int n = in_sizes[i_children] / 256;                // N

    detect_arity_width_kernel<<<1, 256>>>(arities);

    // One warp per row: 256 threads/block = 8 rows/block.
    const int blocks = (n + 7) / 8;
    InterpreterUnit_5858335392361_kernel<<<blocks, 256>>>(
        inputs, children, arities, out, n);
}